// round 11
// baseline (speedup 1.0000x reference)
#include <cuda_runtime.h>

typedef unsigned long long ull;

#define MAXB 4096

static __device__ float g_pos[MAXB];
static __device__ float g_part[32 * MAXB];   // [col-tile][row] partial row sums
static __device__ unsigned g_done = 0;

__device__ __forceinline__ void fma2(ull& d, ull a, ull b) {
    asm("fma.rn.f32x2 %0, %1, %2, %0;" : "+l"(d) : "l"(a), "l"(b));
}
__device__ __forceinline__ ull dup2(float v) {
    ull r;
    asm("mov.b64 %0, {%1, %1};" : "=l"(r) : "r"(__float_as_uint(v)));
    return r;
}
__device__ __forceinline__ float ex2f(float x) {
    float r; asm("ex2.approx.f32 %0, %1;" : "=f"(r) : "f"(x)); return r;
}
__device__ __forceinline__ float lg2f(float x) {
    float r; asm("lg2.approx.f32 %0, %1;" : "=f"(r) : "f"(x)); return r;
}

#define N_A (128 * 64)     // A: [k][64 rows] float, even-XOR swizzle (32 KB)
#define N_B (128 * 128)    // B: [k][128 cols] float, col-quad swizzle (64 KB)

// ---------------- Fused kernel ----------------
// Tile 64 rows x 128 cols, 512 threads = 16 warps, grid (B/128, B/64) = 128 CTAs.
// Warp w: rows w*4..w*4+3 (no split-k, no exchange). Lane l: cols 4l..4l+3.
// Thread micro-tile: 4 rows x 4 cols = 8 packed row-pair accumulators.
// A smem: [k][64] floats, row index swizzled r^h, h=(2*(k>>2))&30 (pairs intact).
// B smem: [k][128] floats, col index swizzled c^s, s=((k>>2)&7)<<2 (quads intact).
// Layouts and addressing identical to the proven R7 kernel; only the
// row-ownership is halved so 16 warps (4/SMSP) hide the LDS latency.
__global__ void __launch_bounds__(512, 1)
hyp_pair(const float* __restrict__ z, const float* __restrict__ zp,
         float* __restrict__ out, int B) {
    extern __shared__ float smem_f[];
    float* As  = smem_f;                      // 32 KB
    float* Bs  = smem_f + N_A;                // 64 KB
    float* sx2 = Bs + N_B;                    // 64
    float* sy2 = sx2 + 64;                    // 128
    float* syi = sy2 + 128;                   // 128
    unsigned* s_rank = (unsigned*)(syi + 128);
    float*    red    = (float*)(s_rank + 8);  // 16 floats

    const int tid  = threadIdx.x;
    const int lane = tid & 31;
    const int warp = tid >> 5;                // 0..15
    const int row0 = blockIdx.y * 64;
    const int col0 = blockIdx.x * 128;

    // ---- fill A: 64 rows x 128 k (coalesced LDG, swizzled transpose, fused row-norm) ----
    {
        const float4* zA = (const float4*)z + row0 * 32;
        #pragma unroll
        for (int p = 0; p < 4; p++) {
            int r = p * 16 + warp;            // warp owns one full row; lanes sweep k-quads
            float4 v = zA[r * 32 + lane];
            int h = (2 * lane) & 30;          // kq = lane
            As[(lane * 4 + 0) * 64 + (r ^ h)] = v.x;
            As[(lane * 4 + 1) * 64 + (r ^ h)] = v.y;
            As[(lane * 4 + 2) * 64 + (r ^ h)] = v.z;
            As[(lane * 4 + 3) * 64 + (r ^ h)] = v.w;
            float s = v.x * v.x + v.y * v.y + v.z * v.z + v.w * v.w;
            #pragma unroll
            for (int o = 16; o; o >>= 1) s += __shfl_xor_sync(0xffffffffu, s, o);
            if (lane == 0) sx2[r] = s;
        }
    }
    // ---- fill B: 128 cols x 128 k (swizzled transpose, fused col-norm) ----
    {
        const float4* zB = (const float4*)zp + col0 * 32;
        #pragma unroll
        for (int p = 0; p < 8; p++) {
            int cj = p * 16 + warp;
            float4 v = zB[cj * 32 + lane];
            int sswz = (lane & 7) << 2;       // kq = lane -> s = ((k>>2)&7)<<2
            Bs[(lane * 4 + 0) * 128 + (cj ^ sswz)] = v.x;
            Bs[(lane * 4 + 1) * 128 + (cj ^ sswz)] = v.y;
            Bs[(lane * 4 + 2) * 128 + (cj ^ sswz)] = v.z;
            Bs[(lane * 4 + 3) * 128 + (cj ^ sswz)] = v.w;
            float s = v.x * v.x + v.y * v.y + v.z * v.z + v.w * v.w;
            #pragma unroll
            for (int o = 16; o; o >>= 1) s += __shfl_xor_sync(0xffffffffu, s, o);
            if (lane == 0) {
                sy2[cj] = s;
                syi[cj] = rsqrtf(fmaxf(s, 1e-24f));   // == 1/max(norm,1e-12)
            }
        }
    }
    __syncthreads();

    ull acc[2][4];                            // [row-pair][col]
    #pragma unroll
    for (int i = 0; i < 2; i++)
        #pragma unroll
        for (int j = 0; j < 4; j++) acc[i][j] = 0ull;

    const int rb   = warp * 4;                // 4 rows per warp
    const int bcol = lane * 4;

    #pragma unroll 8
    for (int kq = 0; kq < 32; kq++) {         // unroll 8 = full swizzle period
        const int h    = (2 * kq) & 30;
        const int sswz = (kq & 7) << 2;
        const float* arow = As + kq * 256;    // 4 k's x 64
        const float* brow = Bs + kq * 512 + (bcol ^ sswz);
        #pragma unroll
        for (int j = 0; j < 4; j++) {
            const float* ar = arow + j * 64;
            ull a0 = *(const ull*)(ar + ((rb + 0) ^ h));   // broadcast row pairs
            ull a1 = *(const ull*)(ar + ((rb + 2) ^ h));
            float4 bv = *(const float4*)(brow + j * 128);  // cols 4l..4l+3
            ull b0 = dup2(bv.x);
            ull b1 = dup2(bv.y);
            ull b2 = dup2(bv.z);
            ull b3 = dup2(bv.w);
            fma2(acc[0][0], a0, b0); fma2(acc[0][1], a0, b1);
            fma2(acc[0][2], a0, b2); fma2(acc[0][3], a0, b3);
            fma2(acc[1][0], a1, b0); fma2(acc[1][1], a1, b1);
            fma2(acc[1][2], a1, b2); fma2(acc[1][3], a1, b3);
        }
    }

    // ---- epilogue: warp owns rows rb..rb+3, thread cols col0 + 4*lane..+3 ----
    {
        float y2v[4], yiv[4];
        #pragma unroll
        for (int c = 0; c < 4; c++) {
            y2v[c] = sy2[bcol + c];
            yiv[c] = syi[bcol + c];
        }
        const float Cc = 0.05f;
        const float SQC = 0.22360679775f;     // sqrt(c)
        #pragma unroll
        for (int rp = 0; rp < 2; rp++) {
            float dv[2][4];
            #pragma unroll
            for (int c = 0; c < 4; c++) {
                unsigned lo, hi;
                asm("mov.b64 {%0, %1}, %2;" : "=r"(lo), "=r"(hi) : "l"(acc[rp][c]));
                dv[0][c] = __uint_as_float(lo);
                dv[1][c] = __uint_as_float(hi);
            }
            #pragma unroll
            for (int hh = 0; hh < 2; hh++) {
                int li = rb + rp * 2 + hh;
                int gi = row0 + li;
                float x2  = sx2[li];
                float xin = rsqrtf(fmaxf(x2, 1e-24f));
                float B1 = 1.0f - Cc * x2;
                float s = 0.0f;
                #pragma unroll
                for (int c = 0; c < 4; c++) {
                    int gj = col0 + bcol + c;
                    float d  = dv[hh][c];                 // <z_i, z'_j>
                    float y2 = y2v[c];
                    float A1  = 1.0f + Cc * (y2 - 2.0f * d);
                    float den = fmaxf(1.0f - 2.0f * Cc * d + Cc * Cc * x2 * y2, 1e-6f);
                    float num = fmaxf(A1 * A1 * x2 - 2.0f * A1 * B1 * d + B1 * B1 * y2, 0.0f);
                    float mn  = num * rsqrtf(fmaxf(num, 1e-37f));   // sqrt(num)
                    float t   = SQC * mn;
                    float pn  = den + t;
                    float qn  = fmaxf(den - t, 1e-6f * den);        // u <= 1-1e-6 guard
                    float l2  = lg2f(pn) - lg2f(qn);                // log2((1+u)/(1-u))
                    float cosv = d * xin * yiv[c];
                    if (gi == gj) {
                        g_pos[gi] = 5.0f * cosv - 15.4993876f * l2; // 22.3607*ln2
                    } else {
                        s += ex2f(7.21347520f * cosv - 22.3606798f * l2);
                    }
                }
                #pragma unroll
                for (int o = 16; o; o >>= 1) s += __shfl_xor_sync(0xffffffffu, s, o);
                if (lane == 0) g_part[blockIdx.x * MAXB + gi] = s;
            }
        }
    }

    // ---- last CTA performs the final reduction (deterministic) ----
    __syncthreads();
    __threadfence();
    if (tid == 0) *s_rank = atomicAdd(&g_done, 1u);
    __syncthreads();
    unsigned nblk = gridDim.x * gridDim.y;
    if (*s_rank == nblk - 1) {
        int nparts = gridDim.x;
        float s = 0.0f;
        for (int i = tid; i < B; i += 512) {
            float dsum = 0.0f;
            #pragma unroll
            for (int p = 0; p < 8; p++) dsum += g_part[p * MAXB + i];
            s += __logf(dsum) - g_pos[i];
        }
        #pragma unroll
        for (int o = 16; o; o >>= 1) s += __shfl_xor_sync(0xffffffffu, s, o);
        if (lane == 0) red[warp] = s;
        __syncthreads();
        if (tid == 0) {
            float tot = 0.0f;
            #pragma unroll
            for (int w = 0; w < 16; w++) tot += red[w];
            out[0] = tot / (float)B;
            g_done = 0;                         // reset for next graph replay
        }
    }
}

extern "C" void kernel_launch(void* const* d_in, const int* in_sizes, int n_in,
                              void* d_out, int out_size) {
    (void)n_in; (void)out_size;
    const float* z  = (const float*)d_in[0];
    const float* zp = (const float*)d_in[1];
    int B = in_sizes[0] / 128;

    int smem = (N_A + N_B) * (int)sizeof(float) + 384 * (int)sizeof(float); // ~97.5 KB
    cudaFuncSetAttribute(hyp_pair, cudaFuncAttributeMaxDynamicSharedMemorySize, smem);
    dim3 grid(B / 128, B / 64);
    hyp_pair<<<grid, 512, smem>>>(z, zp, (float*)d_out, B);
}

// round 12
// speedup vs baseline: 1.2718x; 1.2718x over previous
#include <cuda_runtime.h>
#include <cstdint>

typedef unsigned long long ull;

#define MAXB 4096

static __device__ float g_pos[MAXB];
static __device__ float g_part[32 * MAXB];   // [part = colTile*2 + cw][row]
static __device__ unsigned g_done = 0;

__device__ __forceinline__ float ex2f(float x) {
    float r; asm("ex2.approx.f32 %0, %1;" : "=f"(r) : "f"(x)); return r;
}
__device__ __forceinline__ float lg2f(float x) {
    float r; asm("lg2.approx.f32 %0, %1;" : "=f"(r) : "f"(x)); return r;
}

// m16n8k8 TF32 MMA: D = A(16x8,row) * B(8x8,col) + D, fp32 accum.
__device__ __forceinline__ void mma_tf32(float& c0, float& c1, float& c2, float& c3,
                                         uint32_t a0, uint32_t a1, uint32_t a2, uint32_t a3,
                                         uint32_t b0, uint32_t b1) {
    asm volatile(
        "mma.sync.aligned.m16n8k8.row.col.f32.tf32.tf32.f32 "
        "{%0,%1,%2,%3}, {%4,%5,%6,%7}, {%8,%9}, {%0,%1,%2,%3};"
        : "+f"(c0), "+f"(c1), "+f"(c2), "+f"(c3)
        : "r"(a0), "r"(a1), "r"(a2), "r"(a3), "r"(b0), "r"(b1));
}

#define STRIDE 132                 // 128 + 4 pad floats -> conflict-free fragment LDS
#define N_AS (64 * STRIDE)         // A: [row][k] natural, padded (33 KB)
#define N_BS (128 * STRIDE)        // B: [col][k] natural, padded (66 KB)

// ---------------- Fused kernel ----------------
// Tile 64 rows x 128 cols, 256 threads = 8 warps, grid (B/128, B/64) = 128 CTAs.
// Warp w: row-block rw = w&3 (16 rows), col-group cw = w>>2 (64 cols = 8 n-blocks).
// K loop: 16 steps of k=8 via mma.sync m16n8k8 tf32 (fallback HMMA on sm_103).
// A smem [64][132] fp32 row-major; B smem [128][132] = zp tile [col][k] (= B^T,
// i.e. col-major B as required by .row.col). Fragment scalar LDS are
// bank-conflict-free by the 4-float row pad.
__global__ void __launch_bounds__(256, 1)
hyp_pair(const float* __restrict__ z, const float* __restrict__ zp,
         float* __restrict__ out, int B) {
    extern __shared__ float smem_f[];
    float* As  = smem_f;                      // 33 KB
    float* Bs  = smem_f + N_AS;               // 66 KB
    float* sx2 = Bs + N_BS;                   // 64
    float* sy2 = sx2 + 64;                    // 128
    float* syi = sy2 + 128;                   // 128
    unsigned* s_rank = (unsigned*)(syi + 128);
    float*    red    = (float*)(s_rank + 8);  // 8 floats

    const int tid  = threadIdx.x;
    const int lane = tid & 31;
    const int warp = tid >> 5;
    const int row0 = blockIdx.y * 64;
    const int col0 = blockIdx.x * 128;

    // ---- fill A: 64 rows x 128 k (coalesced LDG, natural padded store, fused row-norm) ----
    {
        const float4* zA = (const float4*)z + row0 * 32;
        #pragma unroll
        for (int p = 0; p < 8; p++) {
            int r = p * 8 + warp;             // warp owns one full row; lanes sweep k
            float4 v = zA[r * 32 + lane];
            *(float4*)(As + r * STRIDE + 4 * lane) = v;
            float s = v.x * v.x + v.y * v.y + v.z * v.z + v.w * v.w;
            #pragma unroll
            for (int o = 16; o; o >>= 1) s += __shfl_xor_sync(0xffffffffu, s, o);
            if (lane == 0) sx2[r] = s;
        }
    }
    // ---- fill B: 128 cols x 128 k (natural padded store, fused col-norm) ----
    {
        const float4* zB = (const float4*)zp + col0 * 32;
        #pragma unroll
        for (int p = 0; p < 16; p++) {
            int cj = p * 8 + warp;
            float4 v = zB[cj * 32 + lane];
            *(float4*)(Bs + cj * STRIDE + 4 * lane) = v;
            float s = v.x * v.x + v.y * v.y + v.z * v.z + v.w * v.w;
            #pragma unroll
            for (int o = 16; o; o >>= 1) s += __shfl_xor_sync(0xffffffffu, s, o);
            if (lane == 0) {
                sy2[cj] = s;
                syi[cj] = rsqrtf(fmaxf(s, 1e-24f));   // == 1/max(norm,1e-12)
            }
        }
    }
    __syncthreads();

    const int rw = warp & 3;                  // row-block (16 rows)
    const int cw = warp >> 2;                 // col-group (64 cols)
    const int g   = lane >> 2;                // groupID
    const int tig = lane & 3;                 // threadID-in-group

    float acc[8][4];                          // [n-block][c-frag]
    #pragma unroll
    for (int nb = 0; nb < 8; nb++)
        #pragma unroll
        for (int c = 0; c < 4; c++) acc[nb][c] = 0.0f;

    const uint32_t* A0 = (const uint32_t*)(As + (rw * 16 + g) * STRIDE + tig);
    const uint32_t* A1 = A0 + 8 * STRIDE;
    const uint32_t* Bp = (const uint32_t*)(Bs + (cw * 64 + g) * STRIDE + tig);

    #pragma unroll
    for (int ks = 0; ks < 16; ks++) {
        const int ko = ks * 8;
        uint32_t a0 = A0[ko];
        uint32_t a1 = A1[ko];
        uint32_t a2 = A0[ko + 4];
        uint32_t a3 = A1[ko + 4];
        #pragma unroll
        for (int nb = 0; nb < 8; nb++) {
            uint32_t b0 = Bp[nb * 8 * STRIDE + ko];
            uint32_t b1 = Bp[nb * 8 * STRIDE + ko + 4];
            mma_tf32(acc[nb][0], acc[nb][1], acc[nb][2], acc[nb][3],
                     a0, a1, a2, a3, b0, b1);
        }
    }

    // ---- epilogue ----
    // Thread owns rows {rw*16+g, +8}, cols cw*64 + nb*8 + 2*tig + {0,1}.
    {
        const float Cc = 0.05f;
        const float SQC = 0.22360679775f;     // sqrt(c)
        float y2v[16], yiv[16];
        #pragma unroll
        for (int nb = 0; nb < 8; nb++)
            #pragma unroll
            for (int c = 0; c < 2; c++) {
                int col = cw * 64 + nb * 8 + 2 * tig + c;
                y2v[nb * 2 + c] = sy2[col];
                yiv[nb * 2 + c] = syi[col];
            }
        #pragma unroll
        for (int half = 0; half < 2; half++) {
            int li = rw * 16 + g + half * 8;
            int gi = row0 + li;
            float x2  = sx2[li];
            float xin = rsqrtf(fmaxf(x2, 1e-24f));
            float B1  = 1.0f - Cc * x2;
            float s = 0.0f;
            #pragma unroll
            for (int nb = 0; nb < 8; nb++) {
                #pragma unroll
                for (int c = 0; c < 2; c++) {
                    int col = cw * 64 + nb * 8 + 2 * tig + c;
                    int gj  = col0 + col;
                    float d  = acc[nb][half * 2 + c];       // <z_i, z'_j>
                    float y2 = y2v[nb * 2 + c];
                    float A1  = 1.0f + Cc * (y2 - 2.0f * d);
                    float den = fmaxf(1.0f - 2.0f * Cc * d + Cc * Cc * x2 * y2, 1e-6f);
                    float num = fmaxf(A1 * A1 * x2 - 2.0f * A1 * B1 * d + B1 * B1 * y2, 0.0f);
                    float mn  = num * rsqrtf(fmaxf(num, 1e-37f));   // sqrt(num)
                    float t   = SQC * mn;
                    float pn  = den + t;
                    float qn  = fmaxf(den - t, 1e-6f * den);        // u <= 1-1e-6 guard
                    float l2  = lg2f(pn) - lg2f(qn);                // log2((1+u)/(1-u))
                    float cosv = d * xin * yiv[nb * 2 + c];
                    if (gi == gj) {
                        g_pos[gi] = 5.0f * cosv - 15.4993876f * l2; // 22.3607*ln2
                    } else {
                        s += ex2f(7.21347520f * cosv - 22.3606798f * l2);
                    }
                }
            }
            // reduce over tig group (lanes g*4 + {0..3} share the row)
            s += __shfl_xor_sync(0xffffffffu, s, 1);
            s += __shfl_xor_sync(0xffffffffu, s, 2);
            if (tig == 0) g_part[(blockIdx.x * 2 + cw) * MAXB + gi] = s;
        }
    }

    // ---- last CTA performs the final reduction (deterministic) ----
    __syncthreads();
    __threadfence();
    if (tid == 0) *s_rank = atomicAdd(&g_done, 1u);
    __syncthreads();
    unsigned nblk = gridDim.x * gridDim.y;
    if (*s_rank == nblk - 1) {
        int nparts = gridDim.x * 2;
        float s = 0.0f;
        for (int i = tid; i < B; i += 256) {
            float dsum = 0.0f;
            #pragma unroll
            for (int p = 0; p < 16; p++) dsum += g_part[p * MAXB + i];
            s += __logf(dsum) - g_pos[i];
        }
        (void)nparts;
        #pragma unroll
        for (int o = 16; o; o >>= 1) s += __shfl_xor_sync(0xffffffffu, s, o);
        if (lane == 0) red[warp] = s;
        __syncthreads();
        if (tid == 0) {
            float tot = 0.0f;
            #pragma unroll
            for (int w = 0; w < 8; w++) tot += red[w];
            out[0] = tot / (float)B;
            g_done = 0;                         // reset for next graph replay
        }
    }
}

extern "C" void kernel_launch(void* const* d_in, const int* in_sizes, int n_in,
                              void* d_out, int out_size) {
    (void)n_in; (void)out_size;
    const float* z  = (const float*)d_in[0];
    const float* zp = (const float*)d_in[1];
    int B = in_sizes[0] / 128;

    int smem = (N_AS + N_BS + 384) * (int)sizeof(float);   // ~101 KB
    cudaFuncSetAttribute(hyp_pair, cudaFuncAttributeMaxDynamicSharedMemorySize, smem);
    dim3 grid(B / 128, B / 64);
    hyp_pair<<<grid, 256, smem>>>(z, zp, (float*)d_out, B);
}

// round 13
// speedup vs baseline: 1.5013x; 1.1805x over previous
#include <cuda_runtime.h>
#include <cstdint>

#define MAXB 4096

static __device__ float g_pos[MAXB];
static __device__ float g_part[32 * MAXB];   // [part = colTile*4 + cw][row]
static __device__ unsigned g_done = 0;

__device__ __forceinline__ float ex2f(float x) {
    float r; asm("ex2.approx.f32 %0, %1;" : "=f"(r) : "f"(x)); return r;
}
__device__ __forceinline__ float lg2f(float x) {
    float r; asm("lg2.approx.f32 %0, %1;" : "=f"(r) : "f"(x)); return r;
}

// m16n8k8 TF32 MMA: D = A(16x8,row) * B(8x8,col) + D, fp32 accum.
__device__ __forceinline__ void mma_tf32(float& c0, float& c1, float& c2, float& c3,
                                         uint32_t a0, uint32_t a1, uint32_t a2, uint32_t a3,
                                         uint32_t b0, uint32_t b1) {
    asm volatile(
        "mma.sync.aligned.m16n8k8.row.col.f32.tf32.tf32.f32 "
        "{%0,%1,%2,%3}, {%4,%5,%6,%7}, {%8,%9}, {%0,%1,%2,%3};"
        : "+f"(c0), "+f"(c1), "+f"(c2), "+f"(c3)
        : "r"(a0), "r"(a1), "r"(a2), "r"(a3), "r"(b0), "r"(b1));
}

#define STRIDE 132                 // 128 + 4 pad floats -> conflict-free fragment LDS
#define N_AS (64 * STRIDE)         // A: [row][k] natural, padded (33 KB)
#define N_BS (128 * STRIDE)        // B: [col][k] natural, padded (66 KB)

// ---------------- Fused kernel ----------------
// Tile 64 rows x 128 cols, 512 threads = 16 warps, grid (B/128, B/64) = 128 CTAs.
// Warp w: row-block rw = w&3 (16 rows), col-group cw = w>>2 (32 cols = 4 n-blocks).
// K loop: 16 steps of k=8 via mma.sync m16n8k8 tf32 (fallback HMMA on sm_103).
// A smem [64][132] fp32 row-major; B smem [128][132] = zp tile [col][k] (col-major
// B as required by .row.col). Fragment scalar LDS conflict-free via the 4-float pad.
__global__ void __launch_bounds__(512, 1)
hyp_pair(const float* __restrict__ z, const float* __restrict__ zp,
         float* __restrict__ out, int B) {
    extern __shared__ float smem_f[];
    float* As  = smem_f;                      // 33 KB
    float* Bs  = smem_f + N_AS;               // 66 KB
    float* sx2 = Bs + N_BS;                   // 64
    float* sy2 = sx2 + 64;                    // 128
    float* syi = sy2 + 128;                   // 128
    unsigned* s_rank = (unsigned*)(syi + 128);
    float*    red    = (float*)(s_rank + 8);  // 16 floats

    const int tid  = threadIdx.x;
    const int lane = tid & 31;
    const int warp = tid >> 5;                // 0..15
    const int row0 = blockIdx.y * 64;
    const int col0 = blockIdx.x * 128;

    // ---- fill A: 64 rows x 128 k (coalesced LDG, natural padded store, fused row-norm) ----
    {
        const float4* zA = (const float4*)z + row0 * 32;
        #pragma unroll
        for (int p = 0; p < 4; p++) {
            int r = p * 16 + warp;            // warp owns one full row; lanes sweep k
            float4 v = zA[r * 32 + lane];
            *(float4*)(As + r * STRIDE + 4 * lane) = v;
            float s = v.x * v.x + v.y * v.y + v.z * v.z + v.w * v.w;
            #pragma unroll
            for (int o = 16; o; o >>= 1) s += __shfl_xor_sync(0xffffffffu, s, o);
            if (lane == 0) sx2[r] = s;
        }
    }
    // ---- fill B: 128 cols x 128 k (natural padded store, fused col-norm) ----
    {
        const float4* zB = (const float4*)zp + col0 * 32;
        #pragma unroll
        for (int p = 0; p < 8; p++) {
            int cj = p * 16 + warp;
            float4 v = zB[cj * 32 + lane];
            *(float4*)(Bs + cj * STRIDE + 4 * lane) = v;
            float s = v.x * v.x + v.y * v.y + v.z * v.z + v.w * v.w;
            #pragma unroll
            for (int o = 16; o; o >>= 1) s += __shfl_xor_sync(0xffffffffu, s, o);
            if (lane == 0) {
                sy2[cj] = s;
                syi[cj] = rsqrtf(fmaxf(s, 1e-24f));   // == 1/max(norm,1e-12)
            }
        }
    }
    __syncthreads();

    const int rw  = warp & 3;                 // row-block (16 rows)
    const int cw  = warp >> 2;                // col-group (32 cols)
    const int g   = lane >> 2;                // groupID
    const int tig = lane & 3;                 // threadID-in-group

    float acc[4][4];                          // [n-block][c-frag]
    #pragma unroll
    for (int nb = 0; nb < 4; nb++)
        #pragma unroll
        for (int c = 0; c < 4; c++) acc[nb][c] = 0.0f;

    const uint32_t* A0 = (const uint32_t*)(As + (rw * 16 + g) * STRIDE + tig);
    const uint32_t* A1 = A0 + 8 * STRIDE;
    const uint32_t* Bp = (const uint32_t*)(Bs + (cw * 32 + g) * STRIDE + tig);

    #pragma unroll
    for (int ks = 0; ks < 16; ks++) {
        const int ko = ks * 8;
        uint32_t a0 = A0[ko];
        uint32_t a1 = A1[ko];
        uint32_t a2 = A0[ko + 4];
        uint32_t a3 = A1[ko + 4];
        #pragma unroll
        for (int nb = 0; nb < 4; nb++) {
            uint32_t b0 = Bp[nb * 8 * STRIDE + ko];
            uint32_t b1 = Bp[nb * 8 * STRIDE + ko + 4];
            mma_tf32(acc[nb][0], acc[nb][1], acc[nb][2], acc[nb][3],
                     a0, a1, a2, a3, b0, b1);
        }
    }

    // ---- epilogue ----
    // Thread owns rows {rw*16+g, +8}, cols cw*32 + nb*8 + 2*tig + {0,1}.
    {
        const float Cc = 0.05f;
        const float SQC = 0.22360679775f;     // sqrt(c)
        float y2v[8], yiv[8];
        #pragma unroll
        for (int nb = 0; nb < 4; nb++)
            #pragma unroll
            for (int c = 0; c < 2; c++) {
                int col = cw * 32 + nb * 8 + 2 * tig + c;
                y2v[nb * 2 + c] = sy2[col];
                yiv[nb * 2 + c] = syi[col];
            }
        #pragma unroll
        for (int half = 0; half < 2; half++) {
            int li = rw * 16 + g + half * 8;
            int gi = row0 + li;
            float x2  = sx2[li];
            float xin = rsqrtf(fmaxf(x2, 1e-24f));
            float B1  = 1.0f - Cc * x2;
            float s = 0.0f;
            #pragma unroll
            for (int nb = 0; nb < 4; nb++) {
                #pragma unroll
                for (int c = 0; c < 2; c++) {
                    int col = cw * 32 + nb * 8 + 2 * tig + c;
                    int gj  = col0 + col;
                    float d  = acc[nb][half * 2 + c];       // <z_i, z'_j>
                    float y2 = y2v[nb * 2 + c];
                    float A1  = 1.0f + Cc * (y2 - 2.0f * d);
                    float den = fmaxf(1.0f - 2.0f * Cc * d + Cc * Cc * x2 * y2, 1e-6f);
                    float num = fmaxf(A1 * A1 * x2 - 2.0f * A1 * B1 * d + B1 * B1 * y2, 0.0f);
                    float mn  = num * rsqrtf(fmaxf(num, 1e-37f));   // sqrt(num)
                    float t   = SQC * mn;
                    float pn  = den + t;
                    float qn  = fmaxf(den - t, 1e-6f * den);        // u <= 1-1e-6 guard
                    float l2  = lg2f(pn) - lg2f(qn);                // log2((1+u)/(1-u))
                    float cosv = d * xin * yiv[nb * 2 + c];
                    if (gi == gj) {
                        g_pos[gi] = 5.0f * cosv - 15.4993876f * l2; // 22.3607*ln2
                    } else {
                        s += ex2f(7.21347520f * cosv - 22.3606798f * l2);
                    }
                }
            }
            // reduce over tig group (lanes g*4 + {0..3} share the row)
            s += __shfl_xor_sync(0xffffffffu, s, 1);
            s += __shfl_xor_sync(0xffffffffu, s, 2);
            if (tig == 0) g_part[(blockIdx.x * 4 + cw) * MAXB + gi] = s;
        }
    }

    // ---- last CTA performs the final reduction (deterministic) ----
    __syncthreads();
    __threadfence();
    if (tid == 0) *s_rank = atomicAdd(&g_done, 1u);
    __syncthreads();
    unsigned nblk = gridDim.x * gridDim.y;
    if (*s_rank == nblk - 1) {
        int nparts = gridDim.x * 4;
        float s = 0.0f;
        for (int i = tid; i < B; i += 512) {
            float dsum = 0.0f;
            #pragma unroll
            for (int p = 0; p < 32; p++) dsum += g_part[p * MAXB + i];
            s += __logf(dsum) - g_pos[i];
        }
        (void)nparts;
        #pragma unroll
        for (int o = 16; o; o >>= 1) s += __shfl_xor_sync(0xffffffffu, s, o);
        if (lane == 0) red[warp] = s;
        __syncthreads();
        if (tid == 0) {
            float tot = 0.0f;
            #pragma unroll
            for (int w = 0; w < 16; w++) tot += red[w];
            out[0] = tot / (float)B;
            g_done = 0;                         // reset for next graph replay
        }
    }
}

extern "C" void kernel_launch(void* const* d_in, const int* in_sizes, int n_in,
                              void* d_out, int out_size) {
    (void)n_in; (void)out_size;
    const float* z  = (const float*)d_in[0];
    const float* zp = (const float*)d_in[1];
    int B = in_sizes[0] / 128;

    int smem = (N_AS + N_BS + 384) * (int)sizeof(float);   // ~101 KB
    cudaFuncSetAttribute(hyp_pair, cudaFuncAttributeMaxDynamicSharedMemorySize, smem);
    dim3 grid(B / 128, B / 64);
    hyp_pair<<<grid, 512, smem>>>(z, zp, (float*)d_out, B);
}